// round 16
// baseline (speedup 1.0000x reference)
#include <cuda_runtime.h>
#include <cstdint>

// RadianceFieldTT — R15: blocked shared-memory GEMM streaming passes (SIMT).
//
//  v0 = core0[d0]
//  pass p (0,1,2): v_{2p+2} = v_{2p} @ C_p[d_{2p+1},d_{2p+2}]
//   - global counting sort by pair digit (64 buckets/pass), buckets PADDED to
//     multiples of 128 -> each 128-sample tile uses exactly ONE 64x64 matrix
//   - tile GEMM per CTA: A[128x64] (transposed in smem) @ W[64x64] (dup {w,w}
//     u64 pairs in smem); thread = 8-sample x 8-col register tile, FFMA2.
//     Lanes read DISTINCT smem data (no broadcast waste), affine addresses.
//  epi: out = v6 @ (W7(d7) @ (payload @ SH(b)))

#define NMAX   (1024 * 256)
#define PPAD   (NMAX + 8192)
#define PTILE  128
#define PTILES (PPAD / PTILE)
#define RANK   64

typedef unsigned long long u64;

__device__ float    g_vA[(size_t)NMAX * 64];
__device__ float    g_vB[(size_t)NMAX * 64];
__device__ float    g_w2[192 * 4096];      // pair products C[r][s], row-major
__device__ int      g_perm[3][PPAD];
__device__ unsigned g_dig[NMAX];
__device__ int      g_cnt[192];
__device__ int      g_cur[192];

__device__ __forceinline__ u64 pk2(float lo, float hi) {
    u64 r; asm("mov.b64 %0, {%1, %2};" : "=l"(r) : "f"(lo), "f"(hi)); return r;
}
__device__ __forceinline__ void upk2(u64 v, float& lo, float& hi) {
    asm("mov.b64 {%0, %1}, %2;" : "=f"(lo), "=f"(hi) : "l"(v));
}
__device__ __forceinline__ u64 ffma2(u64 a, u64 b, u64 c) {
    u64 d; asm("fma.rn.f32x2 %0, %1, %2, %3;" : "=l"(d) : "l"(a), "l"(b), "l"(c)); return d;
}

__device__ __forceinline__ unsigned compute_dig(float cx, float cy, float cz) {
    const int ix = min(255, max(0, (int)floorf((cx * 0.5f + 0.5f) * 256.f)));
    const int iy = min(255, max(0, (int)floorf((cy * 0.5f + 0.5f) * 256.f)));
    const int iz = min(255, max(0, (int)floorf((cz * 0.5f + 0.5f) * 256.f)));
    unsigned dig = 0;
#pragma unroll
    for (int l = 0; l < 8; ++l) {
        const int s = 7 - l;
        const unsigned d = (((ix >> s) & 1) << 2) | (((iy >> s) & 1) << 1) | ((iz >> s) & 1);
        dig |= d << (4 * l);
    }
    return dig;
}
__device__ __forceinline__ int pair_key(unsigned dg, int p) {
    return (int)(((dg >> (4 * (2 * p + 1))) & 7u) * 8u + ((dg >> (4 * (2 * p + 2))) & 7u));
}

// ---------------- sort pipeline ----------------
__global__ void k_zero() { if (threadIdx.x < 192) g_cnt[threadIdx.x] = 0; }

__global__ __launch_bounds__(256) void k_fill() {
    const int i = blockIdx.x * 256 + threadIdx.x;
    if (i < 3 * PPAD) ((int*)g_perm)[i] = -1;
}

__global__ __launch_bounds__(256) void k_keys(const float* __restrict__ coords) {
    __shared__ int lc[192];
    const int t = threadIdx.x;
    if (t < 192) lc[t] = 0;
    __syncthreads();
    const int n = blockIdx.x * 256 + t;
    const unsigned dg = compute_dig(coords[3 * n], coords[3 * n + 1], coords[3 * n + 2]);
    g_dig[n] = dg;
#pragma unroll
    for (int p = 0; p < 3; ++p) atomicAdd(&lc[p * 64 + pair_key(dg, p)], 1);
    __syncthreads();
    if (t < 192 && lc[t]) atomicAdd(&g_cnt[t], lc[t]);
}

// exclusive prefix of PADDED counts (multiple of 128), 3 segments of 64
__global__ __launch_bounds__(192) void k_scan() {
    __shared__ int s[192];
    const int t = threadIdx.x;
    const int v = (g_cnt[t] + 127) & ~127;
    s[t] = v;
    __syncthreads();
#pragma unroll
    for (int off = 1; off < 64; off <<= 1) {
        const int x = ((t & 63) >= off) ? s[t - off] : 0;
        __syncthreads();
        s[t] += x;
        __syncthreads();
    }
    g_cur[t] = s[t] - v;
}

__global__ __launch_bounds__(256) void k_scatter() {
    __shared__ int lc[192], lb[192], lp[192];
    const int t = threadIdx.x;
    if (t < 192) { lc[t] = 0; lp[t] = 0; }
    __syncthreads();
    const int n = blockIdx.x * 256 + t;
    const unsigned dg = g_dig[n];
    int key[3];
#pragma unroll
    for (int p = 0; p < 3; ++p) {
        key[p] = p * 64 + pair_key(dg, p);
        atomicAdd(&lc[key[p]], 1);
    }
    __syncthreads();
    if (t < 192 && lc[t]) lb[t] = atomicAdd(&g_cur[t], lc[t]);
    __syncthreads();
#pragma unroll
    for (int p = 0; p < 3; ++p) {
        const int r = atomicAdd(&lp[key[p]], 1);
        g_perm[p][lb[key[p]] + r] = n;
    }
}

// ---------------- precombine: C = Wa @ Wb, row-major [combo][r][s] ----------
__global__ void __launch_bounds__(256) precombine_kernel(const float* __restrict__ cores)
{
    __shared__ float sA[4096];
    __shared__ float sB[4096];
    const int combo = blockIdx.x;          // p*64 + da*8 + db
    const int p  = combo >> 6;
    const int da = (combo >> 3) & 7;
    const int db = combo & 7;
    const int t = threadIdx.x;

    const float* A  = cores + (size_t)(2 * p) * 32768 + da * 64;
    const float* Bm = cores + (size_t)(2 * p + 1) * 32768 + db * 64;
    for (int i = t; i < 1024; i += 256) {
        const int row = i >> 4, c4 = (i & 15) * 4;
        *(float4*)(sA + row * 64 + c4) = *(const float4*)(A  + row * 512 + c4);
        *(float4*)(sB + row * 64 + c4) = *(const float4*)(Bm + row * 512 + c4);
    }
    __syncthreads();

    const int r  = t >> 2;                 // 0..63
    const int s0 = (t & 3) * 16;
    float acc[16];
#pragma unroll
    for (int i = 0; i < 16; ++i) acc[i] = 0.f;
#pragma unroll 4
    for (int k = 0; k < 64; ++k) {
        const float a = sA[r * 64 + k];
#pragma unroll
        for (int i = 0; i < 16; ++i) acc[i] = fmaf(a, sB[k * 64 + s0 + i], acc[i]);
    }
    float* dst = g_w2 + (size_t)combo * 4096 + r * 64 + s0;
#pragma unroll
    for (int i = 0; i < 16; ++i) dst[i] = acc[i];
}

// ---------------- blocked GEMM streaming pass ----------------
// smem: At[64][128] f32 (32 KB) | B2[64][64] u64 dup (32 KB) | sids (512 B)
#define SM_AT   0
#define SM_B2   32768
#define SM_SID  65536
#define SM_PASS (65536 + 512)

__global__ __launch_bounds__(128) void k_pass(int pass, const float* __restrict__ core0,
                                              const float* __restrict__ vin,
                                              float* __restrict__ vout)
{
    extern __shared__ char smb[];
    float* At  = (float*)(smb + SM_AT);
    u64*   B2  = (u64*)(smb + SM_B2);
    int*   sids = (int*)(smb + SM_SID);

    const int t = threadIdx.x;
    const int base = blockIdx.x * PTILE;

    const int sid0 = g_perm[pass][base];
    if (sid0 < 0) return;                        // beyond-total tile (uniform)
    const int key = pair_key(g_dig[sid0], pass);
    const int sid = g_perm[pass][base + t];
    sids[t] = sid;

    // B2 fill: W row-major -> dup {w,w} u64 pairs (coalesced read + write)
    {
        const float4* W4 = (const float4*)(g_w2 + (size_t)(pass * 64 + key) * 4096);
#pragma unroll
        for (int i = t; i < 1024; i += 128) {
            const float4 w = W4[i];
            u64* d = B2 + 4 * i;
            d[0] = pk2(w.x, w.x); d[1] = pk2(w.y, w.y);
            d[2] = pk2(w.z, w.z); d[3] = pk2(w.w, w.w);
        }
    }
    // A fill transposed: thread t = tile sample-row t; At[k][t] = v[k]
    if (sid >= 0) {
        const float4* src = (pass == 0)
            ? (const float4*)(core0 + (g_dig[sid] & 7u) * RANK)
            : (const float4*)(vin + (size_t)sid * 64);
#pragma unroll
        for (int j = 0; j < 16; ++j) {
            const float4 f = src[j];
            At[(4 * j + 0) * 128 + t] = f.x;
            At[(4 * j + 1) * 128 + t] = f.y;
            At[(4 * j + 2) * 128 + t] = f.z;
            At[(4 * j + 3) * 128 + t] = f.w;
        }
    } else {
#pragma unroll
        for (int k = 0; k < 64; ++k) At[k * 128 + t] = 0.f;
    }
    __syncthreads();

    // compute: thread (sg, cg) -> samples [8*sg, 8*sg+8), cols [8*cg, 8*cg+8)
    const int sg = t >> 3;                 // 0..15
    const int cg = t & 7;                  // 0..7
    u64 acc[32];
#pragma unroll
    for (int i = 0; i < 32; ++i) acc[i] = 0ull;

#pragma unroll 8
    for (int k = 0; k < 64; ++k) {
        const ulonglong2* ar = (const ulonglong2*)((const u64*)(At + k * 128) + sg * 4);
        const ulonglong2 a01 = ar[0];      // samples {8sg+0,1},{8sg+2,3}
        const ulonglong2 a23 = ar[1];      // samples {8sg+4,5},{8sg+6,7}
        const ulonglong2* br = (const ulonglong2*)(B2 + k * 64 + cg * 8);
        const ulonglong2 b01 = br[0];
        const ulonglong2 b23 = br[1];
        const ulonglong2 b45 = br[2];
        const ulonglong2 b67 = br[3];
        const u64 a[4] = {a01.x, a01.y, a23.x, a23.y};
        const u64 b[8] = {b01.x, b01.y, b23.x, b23.y, b45.x, b45.y, b67.x, b67.y};
#pragma unroll
        for (int sp = 0; sp < 4; ++sp)
#pragma unroll
            for (int c = 0; c < 8; ++c)
                acc[sp * 8 + c] = ffma2(a[sp], b[c], acc[sp * 8 + c]);
    }

    // write out: acc[sp][c] = {sample 8sg+2sp (lo), 8sg+2sp+1 (hi)} at col 8cg+c
#pragma unroll
    for (int sp = 0; sp < 4; ++sp) {
        const int r0 = sg * 8 + 2 * sp;
        const int sa = sids[r0], sb = sids[r0 + 1];
        float lo[8], hi[8];
#pragma unroll
        for (int c = 0; c < 8; ++c) upk2(acc[sp * 8 + c], lo[c], hi[c]);
        if (sa >= 0) {
            float* d = vout + (size_t)sa * 64 + cg * 8;
            *(float4*)(d)     = make_float4(lo[0], lo[1], lo[2], lo[3]);
            *(float4*)(d + 4) = make_float4(lo[4], lo[5], lo[6], lo[7]);
        }
        if (sb >= 0) {
            float* d = vout + (size_t)sb * 64 + cg * 8;
            *(float4*)(d)     = make_float4(hi[0], hi[1], hi[2], hi[3]);
            *(float4*)(d + 4) = make_float4(hi[4], hi[5], hi[6], hi[7]);
        }
    }
}

// ---------------- epilogue: fold W7(d7) @ (payload @ SH) ----------------
__global__ __launch_bounds__(256) void k_epi(const float* __restrict__ coords,
                                             const float* __restrict__ viewdirs,
                                             const float* __restrict__ cores,
                                             const float* __restrict__ payload,
                                             float* __restrict__ out, int N)
{
    __shared__ float pp[256];
    __shared__ float wps[8 * 260];
    const int tid = threadIdx.x;
    const int b   = blockIdx.x;
    const int n   = b * 256 + tid;

    const float cx = coords[3 * n + 0];
    const float cy = coords[3 * n + 1];
    const float cz = coords[3 * n + 2];
    const float msk = (fabsf(cx) <= 1.f && fabsf(cy) <= 1.f && fabsf(cz) <= 1.f) ? 1.f : 0.f;
    const int d7 = (int)((g_dig[n] >> 28) & 7u);

    if (tid < RANK) {
        const float* vd = viewdirs + 3 * b;
        const float dx = vd[0], dy = vd[1], dz = vd[2];
        float shv[9];
        shv[0] = 0.28209479177387814f;
        shv[1] = -0.4886025119029199f * dy;
        shv[2] =  0.4886025119029199f * dz;
        shv[3] = -0.4886025119029199f * dx;
        shv[4] =  1.0925484305920792f * dx * dy;
        shv[5] = -1.0925484305920792f * dy * dz;
        shv[6] =  0.31539156525252005f * (2.f * dz * dz - dx * dx - dy * dy);
        shv[7] = -1.0925484305920792f * dx * dz;
        shv[8] =  0.5462742152960396f * (dx * dx - dy * dy);
        const float* pr = payload + tid * 28;
        float s0 = 0.f, s1 = 0.f, s2 = 0.f;
#pragma unroll
        for (int j = 0; j < 9; ++j) {
            s0 = fmaf(pr[j],      shv[j], s0);
            s1 = fmaf(pr[9 + j],  shv[j], s1);
            s2 = fmaf(pr[18 + j], shv[j], s2);
        }
        *(float4*)(pp + 4 * tid) = make_float4(s0, s1, s2, pr[27]);
    }
    __syncthreads();

    // WP[d] = W7(d) @ P'
#pragma unroll
    for (int i = 0; i < 2; ++i) {
        const int idx = tid + i * 256;
        const int d = idx >> 6, r = idx & 63;
        const float* src = cores + (size_t)6 * 32768 + r * 512 + d * 64;
        float a0 = 0.f, a1 = 0.f, a2 = 0.f, a3 = 0.f;
#pragma unroll 4
        for (int s4 = 0; s4 < 16; ++s4) {
            const float4 w4 = *(const float4*)(src + 4 * s4);
            const float4 p0 = *(const float4*)(pp + 4 * (4 * s4 + 0));
            const float4 p1 = *(const float4*)(pp + 4 * (4 * s4 + 1));
            const float4 p2 = *(const float4*)(pp + 4 * (4 * s4 + 2));
            const float4 p3 = *(const float4*)(pp + 4 * (4 * s4 + 3));
            a0 = fmaf(w4.x, p0.x, a0); a1 = fmaf(w4.x, p0.y, a1);
            a2 = fmaf(w4.x, p0.z, a2); a3 = fmaf(w4.x, p0.w, a3);
            a0 = fmaf(w4.y, p1.x, a0); a1 = fmaf(w4.y, p1.y, a1);
            a2 = fmaf(w4.y, p1.z, a2); a3 = fmaf(w4.y, p1.w, a3);
            a0 = fmaf(w4.z, p2.x, a0); a1 = fmaf(w4.z, p2.y, a1);
            a2 = fmaf(w4.z, p2.z, a2); a3 = fmaf(w4.z, p2.w, a3);
            a0 = fmaf(w4.w, p3.x, a0); a1 = fmaf(w4.w, p3.y, a1);
            a2 = fmaf(w4.w, p3.z, a2); a3 = fmaf(w4.w, p3.w, a3);
        }
        *(float4*)(wps + d * 260 + r * 4) = make_float4(a0, a1, a2, a3);
    }
    __syncthreads();

    float o0 = 0.f, o1 = 0.f, o2 = 0.f, o3 = 0.f;
    {
        const float* vrowg = g_vA + (size_t)n * 64;
        const float* wrow = wps + d7 * 260;
#pragma unroll
        for (int q = 0; q < 16; ++q) {
            const float4 t4 = *(const float4*)(vrowg + 4 * q);
            const float4 p0 = *(const float4*)(wrow + 4 * (4 * q + 0));
            const float4 p1 = *(const float4*)(wrow + 4 * (4 * q + 1));
            const float4 p2 = *(const float4*)(wrow + 4 * (4 * q + 2));
            const float4 p3 = *(const float4*)(wrow + 4 * (4 * q + 3));
            o0 = fmaf(t4.x, p0.x, o0); o1 = fmaf(t4.x, p0.y, o1);
            o2 = fmaf(t4.x, p0.z, o2); o3 = fmaf(t4.x, p0.w, o3);
            o0 = fmaf(t4.y, p1.x, o0); o1 = fmaf(t4.y, p1.y, o1);
            o2 = fmaf(t4.y, p1.z, o2); o3 = fmaf(t4.y, p1.w, o3);
            o0 = fmaf(t4.z, p2.x, o0); o1 = fmaf(t4.z, p2.y, o1);
            o2 = fmaf(t4.z, p2.z, o2); o3 = fmaf(t4.z, p2.w, o3);
            o0 = fmaf(t4.w, p3.x, o0); o1 = fmaf(t4.w, p3.y, o1);
            o2 = fmaf(t4.w, p3.z, o2); o3 = fmaf(t4.w, p3.w, o3);
        }
    }
    out[3 * n + 0] = o0 * msk;
    out[3 * n + 1] = o1 * msk;
    out[3 * n + 2] = o2 * msk;
    out[3 * N + n] = o3 * msk;
}

extern "C" void kernel_launch(void* const* d_in, const int* in_sizes, int n_in,
                              void* d_out, int out_size) {
    const float* coords   = (const float*)d_in[0];  // (B,R,3)
    const float* viewdirs = (const float*)d_in[1];  // (B,3)
    const float* core0    = (const float*)d_in[2];  // (1,8,64)
    const float* cores    = (const float*)d_in[3];  // (7,64,8,64)
    const float* payload  = (const float*)d_in[4];  // (64,28)

    const int N = in_sizes[0] / 3;   // 262144
    const int B = in_sizes[1] / 3;   // 1024

    float* vA = nullptr; float* vB = nullptr;
    cudaGetSymbolAddress((void**)&vA, g_vA);
    cudaGetSymbolAddress((void**)&vB, g_vB);

    cudaFuncSetAttribute(k_pass, cudaFuncAttributeMaxDynamicSharedMemorySize, SM_PASS);

    k_zero<<<1, 192>>>();
    k_fill<<<(3 * PPAD + 255) / 256, 256>>>();
    k_keys<<<N / 256, 256>>>(coords);
    k_scan<<<1, 192>>>();
    precombine_kernel<<<192, 256>>>(cores);
    k_scatter<<<N / 256, 256>>>();
    k_pass<<<PTILES, PTILE, SM_PASS>>>(0, core0, vA, vA);
    k_pass<<<PTILES, PTILE, SM_PASS>>>(1, core0, vA, vB);
    k_pass<<<PTILES, PTILE, SM_PASS>>>(2, core0, vB, vA);
    k_epi<<<B, 256>>>(coords, viewdirs, cores, payload, (float*)d_out, N);
}

// round 17
// speedup vs baseline: 1.7913x; 1.7913x over previous
#include <cuda_runtime.h>
#include <cstdint>

// RadianceFieldTT — R16: blocked smem GEMM passes, bank-conflict-free B layout.
//
//  v0 = core0[d0]
//  pass p (0,1,2): v_{2p+2} = v_{2p} @ C_p[d_{2p+1},d_{2p+2}]
//   - global counting sort by pair digit (64 buckets/pass), buckets PADDED to
//     multiples of 128 -> each 128-sample tile uses exactly ONE 64x64 matrix
//   - tile GEMM per CTA: A[128x64] transposed in smem; W dup {w,w} u64 pairs
//     in smem with 80B chunk stride (bank-conflict-free: (cg*20)%32 tiles all
//     banks); thread = 8-sample x 8-col register tile, FFMA2.
//  epi: out = v6 @ (W7(d7) @ (payload @ SH(b)))
//
//  Launch order puts pass0 at position 6 so ncu (-s 5 -c 1) captures it.

#define NMAX   (1024 * 256)
#define PPAD   (NMAX + 8192)
#define PTILE  128
#define PTILES (PPAD / PTILE)
#define RANK   64

typedef unsigned long long u64;

__device__ float    g_vA[(size_t)NMAX * 64];
__device__ float    g_vB[(size_t)NMAX * 64];
__device__ float    g_w2[192 * 4096];      // pair products C[r][s], row-major
__device__ int      g_perm[3][PPAD];
__device__ unsigned g_dig[NMAX];
__device__ int      g_cnt[192];
__device__ int      g_cur[192];

__device__ __forceinline__ u64 pk2(float lo, float hi) {
    u64 r; asm("mov.b64 %0, {%1, %2};" : "=l"(r) : "f"(lo), "f"(hi)); return r;
}
__device__ __forceinline__ void upk2(u64 v, float& lo, float& hi) {
    asm("mov.b64 {%0, %1}, %2;" : "=f"(lo), "=f"(hi) : "l"(v));
}
__device__ __forceinline__ u64 ffma2(u64 a, u64 b, u64 c) {
    u64 d; asm("fma.rn.f32x2 %0, %1, %2, %3;" : "=l"(d) : "l"(a), "l"(b), "l"(c)); return d;
}

__device__ __forceinline__ unsigned compute_dig(float cx, float cy, float cz) {
    const int ix = min(255, max(0, (int)floorf((cx * 0.5f + 0.5f) * 256.f)));
    const int iy = min(255, max(0, (int)floorf((cy * 0.5f + 0.5f) * 256.f)));
    const int iz = min(255, max(0, (int)floorf((cz * 0.5f + 0.5f) * 256.f)));
    unsigned dig = 0;
#pragma unroll
    for (int l = 0; l < 8; ++l) {
        const int s = 7 - l;
        const unsigned d = (((ix >> s) & 1) << 2) | (((iy >> s) & 1) << 1) | ((iz >> s) & 1);
        dig |= d << (4 * l);
    }
    return dig;
}
__device__ __forceinline__ int pair_key(unsigned dg, int p) {
    return (int)(((dg >> (4 * (2 * p + 1))) & 7u) * 8u + ((dg >> (4 * (2 * p + 2))) & 7u));
}

// ---------------- init: zero counters + fill perm with -1 (one kernel) ------
__global__ __launch_bounds__(256) void k_init() {
    const int i = blockIdx.x * 256 + threadIdx.x;
    if (i < 192) g_cnt[i] = 0;
    if (i < 3 * PPAD) ((int*)g_perm)[i] = -1;
}

__global__ __launch_bounds__(256) void k_keys(const float* __restrict__ coords) {
    __shared__ int lc[192];
    const int t = threadIdx.x;
    if (t < 192) lc[t] = 0;
    __syncthreads();
    const int n = blockIdx.x * 256 + t;
    const unsigned dg = compute_dig(coords[3 * n], coords[3 * n + 1], coords[3 * n + 2]);
    g_dig[n] = dg;
#pragma unroll
    for (int p = 0; p < 3; ++p) atomicAdd(&lc[p * 64 + pair_key(dg, p)], 1);
    __syncthreads();
    if (t < 192 && lc[t]) atomicAdd(&g_cnt[t], lc[t]);
}

// exclusive prefix of PADDED counts (multiple of 128), 3 segments of 64
__global__ __launch_bounds__(192) void k_scan() {
    __shared__ int s[192];
    const int t = threadIdx.x;
    const int v = (g_cnt[t] + 127) & ~127;
    s[t] = v;
    __syncthreads();
#pragma unroll
    for (int off = 1; off < 64; off <<= 1) {
        const int x = ((t & 63) >= off) ? s[t - off] : 0;
        __syncthreads();
        s[t] += x;
        __syncthreads();
    }
    g_cur[t] = s[t] - v;
}

__global__ __launch_bounds__(256) void k_scatter() {
    __shared__ int lc[192], lb[192], lp[192];
    const int t = threadIdx.x;
    if (t < 192) { lc[t] = 0; lp[t] = 0; }
    __syncthreads();
    const int n = blockIdx.x * 256 + t;
    const unsigned dg = g_dig[n];
    int key[3];
#pragma unroll
    for (int p = 0; p < 3; ++p) {
        key[p] = p * 64 + pair_key(dg, p);
        atomicAdd(&lc[key[p]], 1);
    }
    __syncthreads();
    if (t < 192 && lc[t]) lb[t] = atomicAdd(&g_cur[t], lc[t]);
    __syncthreads();
#pragma unroll
    for (int p = 0; p < 3; ++p) {
        const int r = atomicAdd(&lp[key[p]], 1);
        g_perm[p][lb[key[p]] + r] = n;
    }
}

// ---------------- precombine: C = Wa @ Wb, row-major [combo][r][s] ----------
__global__ void __launch_bounds__(256) precombine_kernel(const float* __restrict__ cores)
{
    __shared__ float sA[4096];
    __shared__ float sB[4096];
    const int combo = blockIdx.x;          // p*64 + da*8 + db
    const int p  = combo >> 6;
    const int da = (combo >> 3) & 7;
    const int db = combo & 7;
    const int t = threadIdx.x;

    const float* A  = cores + (size_t)(2 * p) * 32768 + da * 64;
    const float* Bm = cores + (size_t)(2 * p + 1) * 32768 + db * 64;
    for (int i = t; i < 1024; i += 256) {
        const int row = i >> 4, c4 = (i & 15) * 4;
        *(float4*)(sA + row * 64 + c4) = *(const float4*)(A  + row * 512 + c4);
        *(float4*)(sB + row * 64 + c4) = *(const float4*)(Bm + row * 512 + c4);
    }
    __syncthreads();

    const int r  = t >> 2;                 // 0..63
    const int s0 = (t & 3) * 16;
    float acc[16];
#pragma unroll
    for (int i = 0; i < 16; ++i) acc[i] = 0.f;
#pragma unroll 4
    for (int k = 0; k < 64; ++k) {
        const float a = sA[r * 64 + k];
#pragma unroll
        for (int i = 0; i < 16; ++i) acc[i] = fmaf(a, sB[k * 64 + s0 + i], acc[i]);
    }
    float* dst = g_w2 + (size_t)combo * 4096 + r * 64 + s0;
#pragma unroll
    for (int i = 0; i < 16; ++i) dst[i] = acc[i];
}

// ---------------- blocked GEMM streaming pass ----------------
// smem: At[64][128] f32 (32 KB) | B2: 64 rows x 8 chunks x 80 B (40960 B) | sids
// B2 chunk (k, cg) at byte k*640 + cg*80: 8 u64 {w,w} for cols 8cg..8cg+7.
// Read banks: base (cg*20)%32 tiles all 32 banks across cg -> conflict-free.
#define SM_AT   0
#define SM_B2   32768
#define SM_SID  (32768 + 40960)
#define SM_PASS (SM_SID + 512)

__global__ __launch_bounds__(128) void k_pass(int pass, const float* __restrict__ core0,
                                              const float* __restrict__ vin,
                                              float* __restrict__ vout)
{
    extern __shared__ char smb[];
    float* At   = (float*)(smb + SM_AT);
    char*  B2   = smb + SM_B2;
    int*   sids = (int*)(smb + SM_SID);

    const int t = threadIdx.x;
    const int base = blockIdx.x * PTILE;

    const int sid0 = g_perm[pass][base];
    if (sid0 < 0) return;                        // wholly-padding tile (uniform)
    const int key = pair_key(g_dig[sid0], pass);
    const int sid = g_perm[pass][base + t];
    sids[t] = sid;

    // B2 fill: chunk i (k = i>>3, cg = i&7) <- W[k][8cg..8cg+7] dup pairs
    {
        const float* W = g_w2 + (size_t)(pass * 64 + key) * 4096;
#pragma unroll
        for (int i = t; i < 512; i += 128) {
            const int k = i >> 3, cg = i & 7;
            const float4 w0 = *(const float4*)(W + k * 64 + cg * 8);
            const float4 w1 = *(const float4*)(W + k * 64 + cg * 8 + 4);
            u64* d = (u64*)(B2 + k * 640 + cg * 80);
            d[0] = pk2(w0.x, w0.x); d[1] = pk2(w0.y, w0.y);
            d[2] = pk2(w0.z, w0.z); d[3] = pk2(w0.w, w0.w);
            d[4] = pk2(w1.x, w1.x); d[5] = pk2(w1.y, w1.y);
            d[6] = pk2(w1.z, w1.z); d[7] = pk2(w1.w, w1.w);
        }
    }
    // A fill transposed: thread t = tile sample-row t; At[k][t] = v[k]
    if (sid >= 0) {
        const float4* src = (pass == 0)
            ? (const float4*)(core0 + (g_dig[sid] & 7u) * RANK)
            : (const float4*)(vin + (size_t)sid * 64);
#pragma unroll
        for (int j = 0; j < 16; ++j) {
            const float4 f = src[j];
            At[(4 * j + 0) * 128 + t] = f.x;
            At[(4 * j + 1) * 128 + t] = f.y;
            At[(4 * j + 2) * 128 + t] = f.z;
            At[(4 * j + 3) * 128 + t] = f.w;
        }
    } else {
#pragma unroll
        for (int k = 0; k < 64; ++k) At[k * 128 + t] = 0.f;
    }
    __syncthreads();

    // compute: thread (sg, cg) -> samples [8*sg, 8*sg+8), cols [8*cg, 8*cg+8)
    const int sg = t >> 3;                 // 0..15
    const int cg = t & 7;                  // 0..7
    const char* bptr = B2 + cg * 80;
    u64 acc[32];
#pragma unroll
    for (int i = 0; i < 32; ++i) acc[i] = 0ull;

#pragma unroll 4
    for (int k = 0; k < 64; ++k) {
        const ulonglong2* ar = (const ulonglong2*)((const u64*)(At + k * 128) + sg * 4);
        const ulonglong2 a01 = ar[0];      // samples {8sg+0,1},{8sg+2,3}
        const ulonglong2 a23 = ar[1];      // samples {8sg+4,5},{8sg+6,7}
        const ulonglong2* br = (const ulonglong2*)(bptr + k * 640);
        const ulonglong2 b01 = br[0];
        const ulonglong2 b23 = br[1];
        const ulonglong2 b45 = br[2];
        const ulonglong2 b67 = br[3];
        const u64 a[4] = {a01.x, a01.y, a23.x, a23.y};
        const u64 b[8] = {b01.x, b01.y, b23.x, b23.y, b45.x, b45.y, b67.x, b67.y};
#pragma unroll
        for (int sp = 0; sp < 4; ++sp)
#pragma unroll
            for (int c = 0; c < 8; ++c)
                acc[sp * 8 + c] = ffma2(a[sp], b[c], acc[sp * 8 + c]);
    }

    // write out: acc[sp][c] = {sample 8sg+2sp (lo), 8sg+2sp+1 (hi)} at col 8cg+c
#pragma unroll
    for (int sp = 0; sp < 4; ++sp) {
        const int r0 = sg * 8 + 2 * sp;
        const int sa = sids[r0], sb = sids[r0 + 1];
        float lo[8], hi[8];
#pragma unroll
        for (int c = 0; c < 8; ++c) upk2(acc[sp * 8 + c], lo[c], hi[c]);
        if (sa >= 0) {
            float* d = vout + (size_t)sa * 64 + cg * 8;
            *(float4*)(d)     = make_float4(lo[0], lo[1], lo[2], lo[3]);
            *(float4*)(d + 4) = make_float4(lo[4], lo[5], lo[6], lo[7]);
        }
        if (sb >= 0) {
            float* d = vout + (size_t)sb * 64 + cg * 8;
            *(float4*)(d)     = make_float4(hi[0], hi[1], hi[2], hi[3]);
            *(float4*)(d + 4) = make_float4(hi[4], hi[5], hi[6], hi[7]);
        }
    }
}

// ---------------- epilogue: fold W7(d7) @ (payload @ SH) ----------------
__global__ __launch_bounds__(256) void k_epi(const float* __restrict__ coords,
                                             const float* __restrict__ viewdirs,
                                             const float* __restrict__ cores,
                                             const float* __restrict__ payload,
                                             float* __restrict__ out, int N)
{
    __shared__ float pp[256];
    __shared__ float wps[8 * 260];
    const int tid = threadIdx.x;
    const int b   = blockIdx.x;
    const int n   = b * 256 + tid;

    const float cx = coords[3 * n + 0];
    const float cy = coords[3 * n + 1];
    const float cz = coords[3 * n + 2];
    const float msk = (fabsf(cx) <= 1.f && fabsf(cy) <= 1.f && fabsf(cz) <= 1.f) ? 1.f : 0.f;
    const int d7 = (int)((g_dig[n] >> 28) & 7u);

    if (tid < RANK) {
        const float* vd = viewdirs + 3 * b;
        const float dx = vd[0], dy = vd[1], dz = vd[2];
        float shv[9];
        shv[0] = 0.28209479177387814f;
        shv[1] = -0.4886025119029199f * dy;
        shv[2] =  0.4886025119029199f * dz;
        shv[3] = -0.4886025119029199f * dx;
        shv[4] =  1.0925484305920792f * dx * dy;
        shv[5] = -1.0925484305920792f * dy * dz;
        shv[6] =  0.31539156525252005f * (2.f * dz * dz - dx * dx - dy * dy);
        shv[7] = -1.0925484305920792f * dx * dz;
        shv[8] =  0.5462742152960396f * (dx * dx - dy * dy);
        const float* pr = payload + tid * 28;
        float s0 = 0.f, s1 = 0.f, s2 = 0.f;
#pragma unroll
        for (int j = 0; j < 9; ++j) {
            s0 = fmaf(pr[j],      shv[j], s0);
            s1 = fmaf(pr[9 + j],  shv[j], s1);
            s2 = fmaf(pr[18 + j], shv[j], s2);
        }
        *(float4*)(pp + 4 * tid) = make_float4(s0, s1, s2, pr[27]);
    }
    __syncthreads();

    // WP[d] = W7(d) @ P'
#pragma unroll
    for (int i = 0; i < 2; ++i) {
        const int idx = tid + i * 256;
        const int d = idx >> 6, r = idx & 63;
        const float* src = cores + (size_t)6 * 32768 + r * 512 + d * 64;
        float a0 = 0.f, a1 = 0.f, a2 = 0.f, a3 = 0.f;
#pragma unroll 4
        for (int s4 = 0; s4 < 16; ++s4) {
            const float4 w4 = *(const float4*)(src + 4 * s4);
            const float4 p0 = *(const float4*)(pp + 4 * (4 * s4 + 0));
            const float4 p1 = *(const float4*)(pp + 4 * (4 * s4 + 1));
            const float4 p2 = *(const float4*)(pp + 4 * (4 * s4 + 2));
            const float4 p3 = *(const float4*)(pp + 4 * (4 * s4 + 3));
            a0 = fmaf(w4.x, p0.x, a0); a1 = fmaf(w4.x, p0.y, a1);
            a2 = fmaf(w4.x, p0.z, a2); a3 = fmaf(w4.x, p0.w, a3);
            a0 = fmaf(w4.y, p1.x, a0); a1 = fmaf(w4.y, p1.y, a1);
            a2 = fmaf(w4.y, p1.z, a2); a3 = fmaf(w4.y, p1.w, a3);
            a0 = fmaf(w4.z, p2.x, a0); a1 = fmaf(w4.z, p2.y, a1);
            a2 = fmaf(w4.z, p2.z, a2); a3 = fmaf(w4.z, p2.w, a3);
            a0 = fmaf(w4.w, p3.x, a0); a1 = fmaf(w4.w, p3.y, a1);
            a2 = fmaf(w4.w, p3.z, a2); a3 = fmaf(w4.w, p3.w, a3);
        }
        *(float4*)(wps + d * 260 + r * 4) = make_float4(a0, a1, a2, a3);
    }
    __syncthreads();

    float o0 = 0.f, o1 = 0.f, o2 = 0.f, o3 = 0.f;
    {
        const float* vrowg = g_vA + (size_t)n * 64;
        const float* wrow = wps + d7 * 260;
#pragma unroll
        for (int q = 0; q < 16; ++q) {
            const float4 t4 = *(const float4*)(vrowg + 4 * q);
            const float4 p0 = *(const float4*)(wrow + 4 * (4 * q + 0));
            const float4 p1 = *(const float4*)(wrow + 4 * (4 * q + 1));
            const float4 p2 = *(const float4*)(wrow + 4 * (4 * q + 2));
            const float4 p3 = *(const float4*)(wrow + 4 * (4 * q + 3));
            o0 = fmaf(t4.x, p0.x, o0); o1 = fmaf(t4.x, p0.y, o1);
            o2 = fmaf(t4.x, p0.z, o2); o3 = fmaf(t4.x, p0.w, o3);
            o0 = fmaf(t4.y, p1.x, o0); o1 = fmaf(t4.y, p1.y, o1);
            o2 = fmaf(t4.y, p1.z, o2); o3 = fmaf(t4.y, p1.w, o3);
            o0 = fmaf(t4.z, p2.x, o0); o1 = fmaf(t4.z, p2.y, o1);
            o2 = fmaf(t4.z, p2.z, o2); o3 = fmaf(t4.z, p2.w, o3);
            o0 = fmaf(t4.w, p3.x, o0); o1 = fmaf(t4.w, p3.y, o1);
            o2 = fmaf(t4.w, p3.z, o2); o3 = fmaf(t4.w, p3.w, o3);
        }
    }
    out[3 * n + 0] = o0 * msk;
    out[3 * n + 1] = o1 * msk;
    out[3 * n + 2] = o2 * msk;
    out[3 * N + n] = o3 * msk;
}

extern "C" void kernel_launch(void* const* d_in, const int* in_sizes, int n_in,
                              void* d_out, int out_size) {
    const float* coords   = (const float*)d_in[0];  // (B,R,3)
    const float* viewdirs = (const float*)d_in[1];  // (B,3)
    const float* core0    = (const float*)d_in[2];  // (1,8,64)
    const float* cores    = (const float*)d_in[3];  // (7,64,8,64)
    const float* payload  = (const float*)d_in[4];  // (64,28)

    const int N = in_sizes[0] / 3;   // 262144
    const int B = in_sizes[1] / 3;   // 1024

    float* vA = nullptr; float* vB = nullptr;
    cudaGetSymbolAddress((void**)&vA, g_vA);
    cudaGetSymbolAddress((void**)&vB, g_vB);

    cudaFuncSetAttribute(k_pass, cudaFuncAttributeMaxDynamicSharedMemorySize, SM_PASS);

    // order chosen so ncu (-s 5 -c 1) captures k_pass(0) as launch #6
    k_init<<<(3 * PPAD + 255) / 256, 256>>>();
    k_keys<<<N / 256, 256>>>(coords);
    k_scan<<<1, 192>>>();
    precombine_kernel<<<192, 256>>>(cores);
    k_scatter<<<N / 256, 256>>>();
    k_pass<<<PTILES, PTILE, SM_PASS>>>(0, core0, vA, vA);
    k_pass<<<PTILES, PTILE, SM_PASS>>>(1, core0, vA, vB);
    k_pass<<<PTILES, PTILE, SM_PASS>>>(2, core0, vB, vA);
    k_epi<<<B, 256>>>(coords, viewdirs, cores, payload, (float*)d_out, N);
}